// round 14
// baseline (speedup 1.0000x reference)
#include <cuda_runtime.h>
#include <cuda_fp16.h>
#include <cstdint>
#include <math.h>

#define BB 64
#define TT 1024
#define JJ 128
#define DD 256
#define TM 128   // t rows per CTA tile

// ---------------- device scratch ----------------
__device__ __align__(16) __half g_Uh[BB * JJ * DD];
__device__ float g_su[BB * JJ];
__device__ float g_rowmax[BB * TT];
__device__ float g_q2cp[8 * BB * DD];   // per-(b,t-chunk) unnormalized partials
__device__ float g_q2c[BB * DD];

// mma.sync m16n8k16 fp16 -> f32
__device__ __forceinline__ void mma16816(float* c, const uint32_t* a, const uint32_t* b) {
    asm volatile(
        "mma.sync.aligned.m16n8k16.row.col.f32.f16.f16.f32 "
        "{%0,%1,%2,%3}, {%4,%5,%6,%7}, {%8,%9}, {%0,%1,%2,%3};"
        : "+f"(c[0]), "+f"(c[1]), "+f"(c[2]), "+f"(c[3])
        : "r"(a[0]), "r"(a[1]), "r"(a[2]), "r"(a[3]), "r"(b[0]), "r"(b[1]));
}
__device__ __forceinline__ void ldsm4(uint32_t* r, uint32_t addr) {
    asm volatile("ldmatrix.sync.aligned.m8n8.x4.shared.b16 {%0,%1,%2,%3}, [%4];"
        : "=r"(r[0]), "=r"(r[1]), "=r"(r[2]), "=r"(r[3]) : "r"(addr));
}
__device__ __forceinline__ void ldsm4t(uint32_t* r, uint32_t addr) {
    asm volatile("ldmatrix.sync.aligned.m8n8.x4.trans.shared.b16 {%0,%1,%2,%3}, [%4];"
        : "=r"(r[0]), "=r"(r[1]), "=r"(r[2]), "=r"(r[3]) : "r"(addr));
}
#define CP_ASYNC16(dst, src) \
    asm volatile("cp.async.cg.shared.global [%0], [%1], 16;" :: "r"(dst), "l"(src))
#define CP_COMMIT() asm volatile("cp.async.commit_group;" ::: "memory")
#define CP_WAIT0()  asm volatile("cp.async.wait_group 0;" ::: "memory")

// ---------------- smem layout (bytes) ----------------
// SA: [128][136] fp16 pitch 272 (A K-chunk, later probs)
// SB: [128][264] fp16 pitch 528 (full U)
#define SA 0u
#define SB 34816u
#define OFF_SSU 102400u
#define OFF_SSH 102912u
#define OFF_RM  103424u
#define OFF_RS  104448u
#define OFF_WHU 105472u
#define OFF_WH  106496u
#define OFF_SBM 107520u
#define OFF_SLM 108032u
#define SMEM_TOTAL 108048u

// ---------------- U fp16 convert + su ----------------
__global__ void usplit_kernel(const float* __restrict__ U, const float* __restrict__ w_u) {
    __shared__ float sSu[64];
    int b = blockIdx.x >> 1, jh = blockIdx.x & 1;
    int tid = threadIdx.x, lane = tid & 31;
    float wu = w_u[tid];
    if (tid < 64) sSu[tid] = 0.f;
    __syncthreads();
    const float* Ub = U + (size_t)b * JJ * DD;
    __half* uh = g_Uh + (size_t)b * JJ * DD;
    for (int r = 0; r < 64; r++) {
        int j = jh * 64 + r;
        float v = Ub[j * DD + tid];
        uh[j * DD + tid] = __float2half_rn(v);
        float p = v * wu;
        #pragma unroll
        for (int o = 16; o; o >>= 1) p += __shfl_xor_sync(0xffffffffu, p, o);
        if (lane == 0) atomicAdd(&sSu[r], p);
    }
    __syncthreads();
    if (tid < 64) g_su[b * JJ + jh * 64 + tid] = sSu[tid];
}

// ---------------- main fused kernel (2 CTAs/SM) ----------------
__global__ void __launch_bounds__(256, 2)
bidaf_main(const float* __restrict__ H, const float* __restrict__ w_h,
           const float* __restrict__ w_hu, float* __restrict__ G) {
    extern __shared__ char smem[];
    const uint32_t sbase = (uint32_t)__cvta_generic_to_shared(smem);
    const int b = blockIdx.y;
    const int t0 = blockIdx.x * TM;
    const int tid = threadIdx.x;
    const int wid = tid >> 5, lane = tid & 31;
    const int g = lane >> 2, qt = lane & 3;
    const int l16 = lane & 15, lh = lane >> 4;

    float* ssu  = (float*)(smem + OFF_SSU);
    float* ssh  = (float*)(smem + OFF_SSH);
    float* sRM  = (float*)(smem + OFF_RM);
    float* sRS  = (float*)(smem + OFF_RS);
    float* sWhu = (float*)(smem + OFF_WHU);
    float* sWh  = (float*)(smem + OFF_WH);
    float* sBM  = (float*)(smem + OFF_SBM);
    float* sLM  = (float*)(smem + OFF_SLM);

    // ---- cp.async U [128 j][256 d] fp16 into SB (pitch 528B) ----
    {
        const char* src = (const char*)(g_Uh + (size_t)b * JJ * DD);
        #pragma unroll
        for (int k = 0; k < 16; k++) {
            int idx = tid + 256 * k;
            int j = idx >> 5, c = idx & 31;
            CP_ASYNC16(sbase + SB + (uint32_t)(j * 528 + c * 16), src + j * 512 + c * 16);
        }
        CP_COMMIT();
    }

    sWhu[tid] = w_hu[tid];
    sWh[tid]  = w_h[tid];
    if (tid < JJ) ssu[tid] = g_su[b * JJ + tid];
    __syncthreads();

    const int wm1 = wid >> 1, wn1 = wid & 1;   // GEMM1: 4x2 warp grid, 32x64 tiles
    float C1[2][8][4];
    #pragma unroll
    for (int mf = 0; mf < 2; mf++)
        #pragma unroll
        for (int nf = 0; nf < 8; nf++)
            #pragma unroll
            for (int q = 0; q < 4; q++) C1[mf][nf][q] = 0.f;
    float shreg[16];
    #pragma unroll
    for (int k = 0; k < 16; k++) shreg[k] = 0.f;

    // ================= GEMM1: S[128t][128j], K=256 in 2 A-chunks =================
    #pragma unroll
    for (int ch = 0; ch < 2; ch++) {
        // --- stage A chunk = fp16(H*w_hu) [128][128] into SA + sh partial ---
        {
            const float4* H4 = (const float4*)(H + ((size_t)(b * TT + t0)) * DD);
            #pragma unroll
            for (int rk = 0; rk < 16; rk++) {
                int row = wid + 8 * rk;
                int d = ch * 128 + lane * 4;
                float4 v = H4[row * 64 + (d >> 2)];
                __half2 p01 = __floats2half2_rn(v.x * sWhu[d],     v.y * sWhu[d + 1]);
                __half2 p23 = __floats2half2_rn(v.z * sWhu[d + 2], v.w * sWhu[d + 3]);
                *(uint2*)(smem + SA + row * 272 + lane * 8) =
                    make_uint2(*(uint32_t*)&p01, *(uint32_t*)&p23);
                float sh = v.x * sWh[d] + v.y * sWh[d + 1] + v.z * sWh[d + 2] + v.w * sWh[d + 3];
                #pragma unroll
                for (int o = 16; o; o >>= 1) sh += __shfl_xor_sync(0xffffffffu, sh, o);
                shreg[rk] += sh;
            }
        }
        if (ch == 0) CP_WAIT0();   // U resident before first MMA
        __syncthreads();

        #pragma unroll
        for (int ks = 0; ks < 8; ks++) {
            uint32_t a[2][4];
            #pragma unroll
            for (int mf = 0; mf < 2; mf++) {
                uint32_t ar = sbase + SA + (uint32_t)((wm1 * 32 + mf * 16 + l16) * 272 + ks * 32 + lh * 16);
                ldsm4(a[mf], ar);
            }
            #pragma unroll
            for (int p = 0; p < 4; p++) {
                uint32_t br = sbase + SB + (uint32_t)((wn1 * 64 + p * 16 + l16) * 528
                                                      + ch * 256 + ks * 32 + lh * 16);
                uint32_t bb[4];
                ldsm4(bb, br);
                uint32_t B0[2] = {bb[0], bb[2]}, B1[2] = {bb[1], bb[3]};
                #pragma unroll
                for (int mf = 0; mf < 2; mf++) {
                    mma16816(C1[mf][2*p],   a[mf], B0);
                    mma16816(C1[mf][2*p+1], a[mf], B1);
                }
            }
        }
        __syncthreads();   // A chunk consumed (next iter restages / probs repack)
    }
    if (lane == 0) {
        #pragma unroll
        for (int k = 0; k < 16; k++) ssh[wid + 8 * k] = shreg[k];
    }

    // ================= softmax over j =================
    #pragma unroll
    for (int mf = 0; mf < 2; mf++) {
        int r0 = wm1 * 32 + mf * 16 + g;
        float m0 = -1e30f, m1 = -1e30f;
        #pragma unroll
        for (int nf = 0; nf < 8; nf++) {
            float2 su2 = *(const float2*)&ssu[wn1 * 64 + nf * 8 + qt * 2];
            C1[mf][nf][0] += su2.x; C1[mf][nf][1] += su2.y;
            C1[mf][nf][2] += su2.x; C1[mf][nf][3] += su2.y;
            m0 = fmaxf(m0, fmaxf(C1[mf][nf][0], C1[mf][nf][1]));
            m1 = fmaxf(m1, fmaxf(C1[mf][nf][2], C1[mf][nf][3]));
        }
        #pragma unroll
        for (int o = 1; o < 4; o <<= 1) {
            m0 = fmaxf(m0, __shfl_xor_sync(0xffffffffu, m0, o));
            m1 = fmaxf(m1, __shfl_xor_sync(0xffffffffu, m1, o));
        }
        if (qt == 0) { sRM[r0 * 2 + wn1] = m0; sRM[(r0 + 8) * 2 + wn1] = m1; }
    }
    __syncthreads();
    #pragma unroll
    for (int mf = 0; mf < 2; mf++) {
        int r0 = wm1 * 32 + mf * 16 + g;
        float M0 = fmaxf(sRM[r0 * 2], sRM[r0 * 2 + 1]);
        float M1 = fmaxf(sRM[(r0 + 8) * 2], sRM[(r0 + 8) * 2 + 1]);
        float s0 = 0.f, s1 = 0.f;
        #pragma unroll
        for (int nf = 0; nf < 8; nf++) {
            C1[mf][nf][0] = __expf(C1[mf][nf][0] - M0);
            C1[mf][nf][1] = __expf(C1[mf][nf][1] - M0);
            C1[mf][nf][2] = __expf(C1[mf][nf][2] - M1);
            C1[mf][nf][3] = __expf(C1[mf][nf][3] - M1);
            s0 += C1[mf][nf][0] + C1[mf][nf][1];
            s1 += C1[mf][nf][2] + C1[mf][nf][3];
        }
        #pragma unroll
        for (int o = 1; o < 4; o <<= 1) {
            s0 += __shfl_xor_sync(0xffffffffu, s0, o);
            s1 += __shfl_xor_sync(0xffffffffu, s1, o);
        }
        if (qt == 0) {
            sRS[r0 * 2 + wn1] = s0; sRS[(r0 + 8) * 2 + wn1] = s1;
            if (wn1 == 0) {
                float rm0 = M0 + ssh[r0], rm1 = M1 + ssh[r0 + 8];
                g_rowmax[b * TT + t0 + r0]     = rm0;
                g_rowmax[b * TT + t0 + r0 + 8] = rm1;
                sBM[r0] = rm0; sBM[r0 + 8] = rm1;
            }
        }
    }
    __syncthreads();
    // normalize + pack probs fp16 into SA (pitch 272B)
    #pragma unroll
    for (int mf = 0; mf < 2; mf++) {
        int r0 = wm1 * 32 + mf * 16 + g;
        float inv0 = 1.f / (sRS[r0 * 2] + sRS[r0 * 2 + 1]);
        float inv1 = 1.f / (sRS[(r0 + 8) * 2] + sRS[(r0 + 8) * 2 + 1]);
        #pragma unroll
        for (int nf = 0; nf < 8; nf++) {
            int col = wn1 * 64 + nf * 8 + qt * 2;
            __half2 p0 = __floats2half2_rn(C1[mf][nf][0] * inv0, C1[mf][nf][1] * inv0);
            __half2 p1 = __floats2half2_rn(C1[mf][nf][2] * inv1, C1[mf][nf][3] * inv1);
            *(uint32_t*)(smem + SA + r0 * 272 + col * 2)       = *(uint32_t*)&p0;
            *(uint32_t*)(smem + SA + (r0 + 8) * 272 + col * 2) = *(uint32_t*)&p1;
        }
    }
    // warp 0: local max over the 128 rowmax values (for split-softmax partials)
    if (tid < 32) {
        float m = fmaxf(fmaxf(sBM[tid], sBM[tid + 32]), fmaxf(sBM[tid + 64], sBM[tid + 96]));
        #pragma unroll
        for (int o = 16; o; o >>= 1) m = fmaxf(m, __shfl_xor_sync(0xffffffffu, m, o));
        if (tid == 0) sLM[0] = m;
    }
    __syncthreads();

    // ================= GEMM2 (1x8 warp grid, 2 M-passes) + direct epilogue =================
    // warp wid owns d-cols [wid*32, wid*32+32) exclusively.
    float qa[4][2];
    #pragma unroll
    for (int nf = 0; nf < 4; nf++) { qa[nf][0] = 0.f; qa[nf][1] = 0.f; }
    const float localM = sLM[0];

    #pragma unroll
    for (int mp = 0; mp < 2; mp++) {
        float C2[4][4][4];
        #pragma unroll
        for (int mf = 0; mf < 4; mf++)
            #pragma unroll
            for (int nf = 0; nf < 4; nf++)
                #pragma unroll
                for (int q = 0; q < 4; q++) C2[mf][nf][q] = 0.f;

        #pragma unroll
        for (int ks = 0; ks < 8; ks++) {
            uint32_t a[4][4];
            #pragma unroll
            for (int mf = 0; mf < 4; mf++) {
                uint32_t ar = sbase + SA + (uint32_t)((mp * 64 + mf * 16 + l16) * 272 + ks * 32 + lh * 16);
                ldsm4(a[mf], ar);
            }
            #pragma unroll
            for (int p = 0; p < 2; p++) {
                uint32_t br = sbase + SB + (uint32_t)((ks * 16 + l16) * 528
                                                      + (wid * 32 + p * 16 + lh * 8) * 2);
                uint32_t bb[4];
                ldsm4t(bb, br);
                uint32_t B0[2] = {bb[0], bb[1]}, B1[2] = {bb[2], bb[3]};
                #pragma unroll
                for (int mf = 0; mf < 4; mf++) {
                    mma16816(C2[mf][2*p],   a[mf], B0);
                    mma16816(C2[mf][2*p+1], a[mf], B1);
                }
            }
        }

        // ---- direct epilogue for this pass: G quarters 0,1,2 + partial Q2C ----
        #pragma unroll
        for (int mf = 0; mf < 4; mf++) {
            #pragma unroll
            for (int h = 0; h < 2; h++) {
                int r = mp * 64 + mf * 16 + g + 8 * h;
                float wgt = __expf(sBM[r] - localM);
                size_t rowg = (size_t)(b * TT + t0 + r);
                const float* Hrow = H + rowg * DD;
                float* Grow = G + rowg * (4 * DD);
                #pragma unroll
                for (int nf = 0; nf < 4; nf++) {
                    int c = wid * 32 + nf * 8 + qt * 2;
                    float2 cq = make_float2(C2[mf][nf][2*h], C2[mf][nf][2*h+1]);
                    float2 hv = *(const float2*)&Hrow[c];
                    *(float2*)&Grow[c] = hv;
                    *(float2*)&Grow[DD + c] = cq;
                    *(float2*)&Grow[2 * DD + c] = make_float2(hv.x * cq.x, hv.y * cq.y);
                    qa[nf][0] += wgt * hv.x;
                    qa[nf][1] += wgt * hv.y;
                }
            }
        }
    }

    // ---- reduce qa over the 8 g-lanes (same qt share the same cols) ----
    #pragma unroll
    for (int nf = 0; nf < 4; nf++) {
        #pragma unroll
        for (int o = 4; o < 32; o <<= 1) {
            qa[nf][0] += __shfl_xor_sync(0xffffffffu, qa[nf][0], o);
            qa[nf][1] += __shfl_xor_sync(0xffffffffu, qa[nf][1], o);
        }
    }
    if (lane < 4) {
        float* dst = g_q2cp + (size_t)(b * 8 + blockIdx.x) * DD;
        #pragma unroll
        for (int nf = 0; nf < 4; nf++) {
            int c = wid * 32 + nf * 8 + lane * 2;
            *(float2*)&dst[c] = make_float2(qa[nf][0], qa[nf][1]);
        }
    }
}

// ---------------- Q2C reduce: recombine 8 split-softmax chunks per batch ----------------
__global__ void q2cr_kernel() {
    __shared__ float sM[8], sS[8];
    int b = blockIdx.x;
    int tid = threadIdx.x;
    int w = tid >> 5, lane = tid & 31;
    {
        float v[4], m = -1e30f;
        #pragma unroll
        for (int k = 0; k < 4; k++) {
            v[k] = g_rowmax[b * TT + w * 128 + lane + 32 * k];
            m = fmaxf(m, v[k]);
        }
        #pragma unroll
        for (int o = 16; o; o >>= 1) m = fmaxf(m, __shfl_xor_sync(0xffffffffu, m, o));
        float s = 0.f;
        #pragma unroll
        for (int k = 0; k < 4; k++) s += __expf(v[k] - m);
        #pragma unroll
        for (int o = 16; o; o >>= 1) s += __shfl_xor_sync(0xffffffffu, s, o);
        if (lane == 0) { sM[w] = m; sS[w] = s; }
    }
    __syncthreads();
    float Mg = sM[0];
    #pragma unroll
    for (int c = 1; c < 8; c++) Mg = fmaxf(Mg, sM[c]);
    float denom = 0.f, acc = 0.f;
    #pragma unroll
    for (int c = 0; c < 8; c++) {
        float sc = __expf(sM[c] - Mg);
        denom += sc * sS[c];
        acc   += sc * g_q2cp[(size_t)(b * 8 + c) * DD + tid];
    }
    g_q2c[b * DD + tid] = acc / denom;
}

// ---------------- G quarter 3 = H * Q2C ----------------
__global__ void g3_kernel(const float* __restrict__ H, float* __restrict__ G) {
    size_t base = (size_t)blockIdx.x * 1024 + threadIdx.x;
    #pragma unroll
    for (int k = 0; k < 4; k++) {
        size_t idx = base + 256 * k;           // float4 units
        int d4 = (int)(idx & 63);
        size_t bt = idx >> 6;
        int b = (int)(bt >> 10);
        float4 h = ((const float4*)H)[idx];
        float4 q = ((const float4*)g_q2c)[b * 64 + d4];
        float4 o = make_float4(h.x * q.x, h.y * q.y, h.z * q.z, h.w * q.w);
        ((float4*)G)[bt * 256 + 192 + d4] = o;
    }
}

extern "C" void kernel_launch(void* const* d_in, const int* in_sizes, int n_in,
                              void* d_out, int out_size) {
    const float* H    = (const float*)d_in[0];
    const float* U    = (const float*)d_in[1];
    const float* w_h  = (const float*)d_in[2];
    const float* w_u  = (const float*)d_in[3];
    const float* w_hu = (const float*)d_in[4];
    float* G = (float*)d_out;

    cudaFuncSetAttribute(bidaf_main, cudaFuncAttributeMaxDynamicSharedMemorySize, SMEM_TOTAL);

    usplit_kernel<<<BB * 2, 256>>>(U, w_u);
    bidaf_main<<<dim3(TT / TM, BB), 256, SMEM_TOTAL>>>(H, w_h, w_hu, G);
    q2cr_kernel<<<BB, 256>>>();
    g3_kernel<<<(BB * TT * DD / 4) / 1024, 256>>>(H, G);
}

// round 15
// speedup vs baseline: 1.4266x; 1.4266x over previous
#include <cuda_runtime.h>
#include <cuda_fp16.h>
#include <cstdint>
#include <math.h>

#define BB 64
#define TT 1024
#define JJ 128
#define DD 256
#define TM 128   // t rows per CTA tile

// ---------------- device scratch ----------------
__device__ __align__(16) __half g_Uh[BB * JJ * DD];
__device__ float g_su[BB * JJ];
__device__ float g_rowmax[BB * TT];
__device__ float g_q2cp[8 * BB * DD];   // per-(b,t-chunk) unnormalized partials
__device__ float g_q2c[BB * DD];

// mma.sync m16n8k16 fp16 -> f32
__device__ __forceinline__ void mma16816(float* c, const uint32_t* a, const uint32_t* b) {
    asm volatile(
        "mma.sync.aligned.m16n8k16.row.col.f32.f16.f16.f32 "
        "{%0,%1,%2,%3}, {%4,%5,%6,%7}, {%8,%9}, {%0,%1,%2,%3};"
        : "+f"(c[0]), "+f"(c[1]), "+f"(c[2]), "+f"(c[3])
        : "r"(a[0]), "r"(a[1]), "r"(a[2]), "r"(a[3]), "r"(b[0]), "r"(b[1]));
}
__device__ __forceinline__ void ldsm4(uint32_t* r, uint32_t addr) {
    asm volatile("ldmatrix.sync.aligned.m8n8.x4.shared.b16 {%0,%1,%2,%3}, [%4];"
        : "=r"(r[0]), "=r"(r[1]), "=r"(r[2]), "=r"(r[3]) : "r"(addr));
}
__device__ __forceinline__ void ldsm4t(uint32_t* r, uint32_t addr) {
    asm volatile("ldmatrix.sync.aligned.m8n8.x4.trans.shared.b16 {%0,%1,%2,%3}, [%4];"
        : "=r"(r[0]), "=r"(r[1]), "=r"(r[2]), "=r"(r[3]) : "r"(addr));
}
#define CP_ASYNC16(dst, src) \
    asm volatile("cp.async.cg.shared.global [%0], [%1], 16;" :: "r"(dst), "l"(src))
#define CP_COMMIT() asm volatile("cp.async.commit_group;" ::: "memory")
#define CP_WAIT0()  asm volatile("cp.async.wait_group 0;" ::: "memory")

// ---------------- smem layout (bytes) ----------------
// SA: [128 t][264] fp16 (A full-K; later probs at pitch 272B), pitch 528B
// SB: [128 j][264] fp16 (U full), pitch 528B
// epilogue f32 [128][264] overlays SA+SB
#define SA 0u
#define SB 67584u
#define OFF_SSU 135168u
#define OFF_SSH 135680u
#define OFF_RM  136192u
#define OFF_RS  137216u
#define OFF_WHU 138240u
#define OFF_WH  139264u
#define OFF_SBM 140288u   // [128] rowmax (f32)
#define OFF_SLM 140800u   // scalar localM (padded 16B)
#define OFF_SQ  140816u   // [8][256] f32 partial-q2c reduce
#define SMEM_TOTAL 149008u

// ---------------- U fp16 convert + su (512 blocks, 16 rows each) ----------------
__global__ void usplit_kernel(const float* __restrict__ U, const float* __restrict__ w_u) {
    __shared__ float sSu[16];
    int b = blockIdx.x >> 3, jc = blockIdx.x & 7;
    int tid = threadIdx.x, lane = tid & 31;
    float wu = w_u[tid];
    if (tid < 16) sSu[tid] = 0.f;
    __syncthreads();
    const float* Ub = U + (size_t)b * JJ * DD;
    __half* uh = g_Uh + (size_t)b * JJ * DD;
    #pragma unroll
    for (int r = 0; r < 16; r++) {
        int j = jc * 16 + r;
        float v = Ub[j * DD + tid];
        uh[j * DD + tid] = __float2half_rn(v);
        float p = v * wu;
        #pragma unroll
        for (int o = 16; o; o >>= 1) p += __shfl_xor_sync(0xffffffffu, p, o);
        if (lane == 0) atomicAdd(&sSu[r], p);
    }
    __syncthreads();
    if (tid < 16) g_su[b * JJ + jc * 16 + tid] = sSu[tid];
}

// ---------------- main fused kernel ----------------
__global__ void __launch_bounds__(256, 1)
bidaf_main(const float* __restrict__ H, const float* __restrict__ w_h,
           const float* __restrict__ w_hu, float* __restrict__ G) {
    extern __shared__ char smem[];
    const uint32_t sbase = (uint32_t)__cvta_generic_to_shared(smem);
    const int b = blockIdx.y;
    const int t0 = blockIdx.x * TM;
    const int tid = threadIdx.x;
    const int wid = tid >> 5, lane = tid & 31;
    const int g = lane >> 2, qt = lane & 3;
    const int l16 = lane & 15, lh = lane >> 4;

    float* ssu  = (float*)(smem + OFF_SSU);
    float* ssh  = (float*)(smem + OFF_SSH);
    float* sRM  = (float*)(smem + OFF_RM);
    float* sRS  = (float*)(smem + OFF_RS);
    float* sWhu = (float*)(smem + OFF_WHU);
    float* sWh  = (float*)(smem + OFF_WH);
    float* sBM  = (float*)(smem + OFF_SBM);
    float* sLM  = (float*)(smem + OFF_SLM);
    float* sQ   = (float*)(smem + OFF_SQ);

    // ---- cp.async U [128 j][256 d] fp16 into SB (pitch 528B) ----
    {
        const char* src = (const char*)(g_Uh + (size_t)b * JJ * DD);
        #pragma unroll
        for (int k = 0; k < 16; k++) {
            int idx = tid + 256 * k;
            int j = idx >> 5, c = idx & 31;
            CP_ASYNC16(sbase + SB + (uint32_t)(j * 528 + c * 16), src + j * 512 + c * 16);
        }
        CP_COMMIT();
    }

    sWhu[tid] = w_hu[tid];
    sWh[tid]  = w_h[tid];
    if (tid < JJ) ssu[tid] = g_su[b * JJ + tid];
    __syncthreads();

    // ---- stage A = fp16(H*w_hu) full-K [128][256] + sh accumulation ----
    float shreg[16];
    {
        const float4* H4 = (const float4*)(H + ((size_t)(b * TT + t0)) * DD);
        #pragma unroll
        for (int rk = 0; rk < 16; rk++) {
            int row = wid + 8 * rk;
            float sh = 0.f;
            #pragma unroll
            for (int h = 0; h < 2; h++) {
                int d = h * 128 + lane * 4;
                float4 v = H4[row * 64 + (d >> 2)];
                __half2 p01 = __floats2half2_rn(v.x * sWhu[d],     v.y * sWhu[d + 1]);
                __half2 p23 = __floats2half2_rn(v.z * sWhu[d + 2], v.w * sWhu[d + 3]);
                *(uint2*)(smem + SA + row * 528 + d * 2) =
                    make_uint2(*(uint32_t*)&p01, *(uint32_t*)&p23);
                sh += v.x * sWh[d] + v.y * sWh[d + 1] + v.z * sWh[d + 2] + v.w * sWh[d + 3];
            }
            #pragma unroll
            for (int o = 16; o; o >>= 1) sh += __shfl_xor_sync(0xffffffffu, sh, o);
            shreg[rk] = sh;
        }
    }
    if (lane == 0) {
        #pragma unroll
        for (int k = 0; k < 16; k++) ssh[wid + 8 * k] = shreg[k];
    }

    const int wm1 = wid >> 1, wn1 = wid & 1;   // 4x2 warp grid, 32x64 tiles
    float C1[2][8][4];
    #pragma unroll
    for (int mf = 0; mf < 2; mf++)
        #pragma unroll
        for (int nf = 0; nf < 8; nf++)
            #pragma unroll
            for (int q = 0; q < 4; q++) C1[mf][nf][q] = 0.f;

    CP_WAIT0();
    __syncthreads();

    // ================= GEMM1: S[128t][128j], K=256, single pass =================
    #pragma unroll
    for (int ks = 0; ks < 16; ks++) {
        uint32_t a[2][4];
        #pragma unroll
        for (int mf = 0; mf < 2; mf++) {
            uint32_t ar = sbase + SA + (uint32_t)((wm1 * 32 + mf * 16 + l16) * 528 + ks * 32 + lh * 16);
            ldsm4(a[mf], ar);
        }
        #pragma unroll
        for (int p = 0; p < 4; p++) {
            uint32_t br = sbase + SB + (uint32_t)((wn1 * 64 + p * 16 + l16) * 528 + ks * 32 + lh * 16);
            uint32_t bb[4];
            ldsm4(bb, br);
            uint32_t B0[2] = {bb[0], bb[2]}, B1[2] = {bb[1], bb[3]};
            #pragma unroll
            for (int mf = 0; mf < 2; mf++) {
                mma16816(C1[mf][2*p],   a[mf], B0);
                mma16816(C1[mf][2*p+1], a[mf], B1);
            }
        }
    }
    __syncthreads();   // A dead; SA reused for probs below

    // ================= softmax over j =================
    #pragma unroll
    for (int mf = 0; mf < 2; mf++) {
        int r0 = wm1 * 32 + mf * 16 + g;
        float m0 = -1e30f, m1 = -1e30f;
        #pragma unroll
        for (int nf = 0; nf < 8; nf++) {
            float2 su2 = *(const float2*)&ssu[wn1 * 64 + nf * 8 + qt * 2];
            C1[mf][nf][0] += su2.x; C1[mf][nf][1] += su2.y;
            C1[mf][nf][2] += su2.x; C1[mf][nf][3] += su2.y;
            m0 = fmaxf(m0, fmaxf(C1[mf][nf][0], C1[mf][nf][1]));
            m1 = fmaxf(m1, fmaxf(C1[mf][nf][2], C1[mf][nf][3]));
        }
        #pragma unroll
        for (int o = 1; o < 4; o <<= 1) {
            m0 = fmaxf(m0, __shfl_xor_sync(0xffffffffu, m0, o));
            m1 = fmaxf(m1, __shfl_xor_sync(0xffffffffu, m1, o));
        }
        if (qt == 0) { sRM[r0 * 2 + wn1] = m0; sRM[(r0 + 8) * 2 + wn1] = m1; }
    }
    __syncthreads();
    #pragma unroll
    for (int mf = 0; mf < 2; mf++) {
        int r0 = wm1 * 32 + mf * 16 + g;
        float M0 = fmaxf(sRM[r0 * 2], sRM[r0 * 2 + 1]);
        float M1 = fmaxf(sRM[(r0 + 8) * 2], sRM[(r0 + 8) * 2 + 1]);
        float s0 = 0.f, s1 = 0.f;
        #pragma unroll
        for (int nf = 0; nf < 8; nf++) {
            C1[mf][nf][0] = __expf(C1[mf][nf][0] - M0);
            C1[mf][nf][1] = __expf(C1[mf][nf][1] - M0);
            C1[mf][nf][2] = __expf(C1[mf][nf][2] - M1);
            C1[mf][nf][3] = __expf(C1[mf][nf][3] - M1);
            s0 += C1[mf][nf][0] + C1[mf][nf][1];
            s1 += C1[mf][nf][2] + C1[mf][nf][3];
        }
        #pragma unroll
        for (int o = 1; o < 4; o <<= 1) {
            s0 += __shfl_xor_sync(0xffffffffu, s0, o);
            s1 += __shfl_xor_sync(0xffffffffu, s1, o);
        }
        if (qt == 0) {
            sRS[r0 * 2 + wn1] = s0; sRS[(r0 + 8) * 2 + wn1] = s1;
            if (wn1 == 0) {
                float rm0 = M0 + ssh[r0], rm1 = M1 + ssh[r0 + 8];
                g_rowmax[b * TT + t0 + r0]     = rm0;
                g_rowmax[b * TT + t0 + r0 + 8] = rm1;
                sBM[r0] = rm0; sBM[r0 + 8] = rm1;
            }
        }
    }
    __syncthreads();
    // normalize + pack probs fp16 into SA (pitch 272B)
    #pragma unroll
    for (int mf = 0; mf < 2; mf++) {
        int r0 = wm1 * 32 + mf * 16 + g;
        float inv0 = 1.f / (sRS[r0 * 2] + sRS[r0 * 2 + 1]);
        float inv1 = 1.f / (sRS[(r0 + 8) * 2] + sRS[(r0 + 8) * 2 + 1]);
        #pragma unroll
        for (int nf = 0; nf < 8; nf++) {
            int col = wn1 * 64 + nf * 8 + qt * 2;
            __half2 p0 = __floats2half2_rn(C1[mf][nf][0] * inv0, C1[mf][nf][1] * inv0);
            __half2 p1 = __floats2half2_rn(C1[mf][nf][2] * inv1, C1[mf][nf][3] * inv1);
            *(uint32_t*)(smem + SA + r0 * 272 + col * 2)       = *(uint32_t*)&p0;
            *(uint32_t*)(smem + SA + (r0 + 8) * 272 + col * 2) = *(uint32_t*)&p1;
        }
    }
    // warp 0: local max over the 128 rowmax values (for split-softmax partials)
    if (tid < 32) {
        float m = fmaxf(fmaxf(sBM[tid], sBM[tid + 32]), fmaxf(sBM[tid + 64], sBM[tid + 96]));
        #pragma unroll
        for (int o = 16; o; o >>= 1) m = fmaxf(m, __shfl_xor_sync(0xffffffffu, m, o));
        if (tid == 0) sLM[0] = m;
    }
    __syncthreads();

    // ================= GEMM2: C2Q[128t][256d] = P @ U (trans-B on U) =================
    const int wm2 = wid >> 2, wn2 = wid & 3;   // 2x4 warp grid, 64x64 tiles
    float C2[4][8][4];
    #pragma unroll
    for (int mf = 0; mf < 4; mf++)
        #pragma unroll
        for (int nf = 0; nf < 8; nf++)
            #pragma unroll
            for (int q = 0; q < 4; q++) C2[mf][nf][q] = 0.f;

    #pragma unroll
    for (int ks = 0; ks < 8; ks++) {
        uint32_t a[4][4];
        #pragma unroll
        for (int mf = 0; mf < 4; mf++) {
            uint32_t ar = sbase + SA + (uint32_t)((wm2 * 64 + mf * 16 + l16) * 272 + ks * 32 + lh * 16);
            ldsm4(a[mf], ar);
        }
        #pragma unroll
        for (int p = 0; p < 4; p++) {
            uint32_t br = sbase + SB + (uint32_t)((ks * 16 + l16) * 528
                                                  + (wn2 * 64 + p * 16 + lh * 8) * 2);
            uint32_t bb[4];
            ldsm4t(bb, br);
            uint32_t B0[2] = {bb[0], bb[1]}, B1[2] = {bb[2], bb[3]};
            #pragma unroll
            for (int mf = 0; mf < 4; mf++) {
                mma16816(C2[mf][2*p],   a[mf], B0);
                mma16816(C2[mf][2*p+1], a[mf], B1);
            }
        }
    }
    __syncthreads();   // SA+SB dead -> f32 epilogue buffer overlays from 0

    // ================= epilogue: G quarters 0,1,2 + partial Q2C =================
    {
        float* sEpi = (float*)smem;            // [128][264] f32
        #pragma unroll
        for (int mf = 0; mf < 4; mf++) {
            int r0 = wm2 * 64 + mf * 16 + g;
            #pragma unroll
            for (int nf = 0; nf < 8; nf++) {
                int c0 = wn2 * 64 + nf * 8 + qt * 2;
                *(float2*)&sEpi[r0 * 264 + c0]       = make_float2(C2[mf][nf][0], C2[mf][nf][1]);
                *(float2*)&sEpi[(r0 + 8) * 264 + c0] = make_float2(C2[mf][nf][2], C2[mf][nf][3]);
            }
        }
        __syncthreads();
        const float localM = sLM[0];
        float4 qa0 = make_float4(0.f, 0.f, 0.f, 0.f);
        float4 qa1 = make_float4(0.f, 0.f, 0.f, 0.f);
        #pragma unroll 2
        for (int r = 0; r < 16; r++) {
            int row = wid * 16 + r;
            float wgt = __expf(sBM[row] - localM);
            size_t rowg = (size_t)(b * TT + t0 + row);
            const float* Hrow = H + rowg * DD;
            float* Grow = G + rowg * (4 * DD);
            #pragma unroll
            for (int i = 0; i < 2; i++) {
                int d = lane * 4 + 128 * i;
                float4 cq = *(float4*)&sEpi[row * 264 + d];
                float4 h = *(const float4*)&Hrow[d];
                *(float4*)&Grow[d] = h;
                *(float4*)&Grow[DD + d] = cq;
                *(float4*)&Grow[2 * DD + d] = make_float4(h.x*cq.x, h.y*cq.y, h.z*cq.z, h.w*cq.w);
                if (i == 0) { qa0.x += wgt*h.x; qa0.y += wgt*h.y; qa0.z += wgt*h.z; qa0.w += wgt*h.w; }
                else        { qa1.x += wgt*h.x; qa1.y += wgt*h.y; qa1.z += wgt*h.z; qa1.w += wgt*h.w; }
            }
        }
        *(float4*)&sQ[wid * 256 + lane * 4]       = qa0;
        *(float4*)&sQ[wid * 256 + lane * 4 + 128] = qa1;
        __syncthreads();
        {
            float s = 0.f;
            #pragma unroll
            for (int w = 0; w < 8; w++) s += sQ[w * 256 + tid];
            g_q2cp[(size_t)(b * 8 + blockIdx.x) * DD + tid] = s;
        }
    }
}

// ---------------- Q2C reduce: recombine 8 split-softmax chunks per batch ----------------
__global__ void q2cr_kernel() {
    __shared__ float sM[8], sS[8];
    int b = blockIdx.x;
    int tid = threadIdx.x;
    int w = tid >> 5, lane = tid & 31;
    // warp w recomputes chunk-w max and sumexp from g_rowmax
    {
        float v[4], m = -1e30f;
        #pragma unroll
        for (int k = 0; k < 4; k++) {
            v[k] = g_rowmax[b * TT + w * 128 + lane + 32 * k];
            m = fmaxf(m, v[k]);
        }
        #pragma unroll
        for (int o = 16; o; o >>= 1) m = fmaxf(m, __shfl_xor_sync(0xffffffffu, m, o));
        float s = 0.f;
        #pragma unroll
        for (int k = 0; k < 4; k++) s += __expf(v[k] - m);
        #pragma unroll
        for (int o = 16; o; o >>= 1) s += __shfl_xor_sync(0xffffffffu, s, o);
        if (lane == 0) { sM[w] = m; sS[w] = s; }
    }
    __syncthreads();
    float Mg = sM[0];
    #pragma unroll
    for (int c = 1; c < 8; c++) Mg = fmaxf(Mg, sM[c]);
    float denom = 0.f, acc = 0.f;
    #pragma unroll
    for (int c = 0; c < 8; c++) {
        float sc = __expf(sM[c] - Mg);
        denom += sc * sS[c];
        acc   += sc * g_q2cp[(size_t)(b * 8 + c) * DD + tid];
    }
    g_q2c[b * DD + tid] = acc / denom;
}

// ---------------- G quarter 3 = H * Q2C (8 float4 per thread) ----------------
__global__ void g3_kernel(const float* __restrict__ H, float* __restrict__ G) {
    size_t base = (size_t)blockIdx.x * 2048 + threadIdx.x;
    #pragma unroll
    for (int k = 0; k < 8; k++) {
        size_t idx = base + 256 * k;           // float4 units
        int d4 = (int)(idx & 63);
        size_t bt = idx >> 6;
        int b = (int)(bt >> 10);
        float4 h = ((const float4*)H)[idx];
        float4 q = ((const float4*)g_q2c)[b * 64 + d4];
        float4 o = make_float4(h.x * q.x, h.y * q.y, h.z * q.z, h.w * q.w);
        ((float4*)G)[bt * 256 + 192 + d4] = o;
    }
}

extern "C" void kernel_launch(void* const* d_in, const int* in_sizes, int n_in,
                              void* d_out, int out_size) {
    const float* H    = (const float*)d_in[0];
    const float* U    = (const float*)d_in[1];
    const float* w_h  = (const float*)d_in[2];
    const float* w_u  = (const float*)d_in[3];
    const float* w_hu = (const float*)d_in[4];
    float* G = (float*)d_out;

    cudaFuncSetAttribute(bidaf_main, cudaFuncAttributeMaxDynamicSharedMemorySize, SMEM_TOTAL);

    usplit_kernel<<<BB * 8, 256>>>(U, w_u);
    bidaf_main<<<dim3(TT / TM, BB), 256, SMEM_TOTAL>>>(H, w_h, w_hu, G);
    q2cr_kernel<<<BB, 256>>>();
    g3_kernel<<<(BB * TT * DD / 4) / 2048, 256>>>(H, G);
}

// round 17
// speedup vs baseline: 1.5124x; 1.0601x over previous
#include <cuda_runtime.h>
#include <cuda_fp16.h>
#include <cstdint>
#include <math.h>

#define BB 64
#define TT 1024
#define JJ 128
#define DD 256
#define TM 128   // t rows per CTA tile

// ---------------- device scratch ----------------
__device__ __align__(16) __half g_Uh[BB * JJ * DD];
__device__ float g_su[BB * JJ];
__device__ float g_rowmax[BB * TT];
__device__ float g_q2cp[8 * BB * DD];   // per-(b,t-chunk) unnormalized partials

// mma.sync m16n8k16 fp16 -> f32
__device__ __forceinline__ void mma16816(float* c, const uint32_t* a, const uint32_t* b) {
    asm volatile(
        "mma.sync.aligned.m16n8k16.row.col.f32.f16.f16.f32 "
        "{%0,%1,%2,%3}, {%4,%5,%6,%7}, {%8,%9}, {%0,%1,%2,%3};"
        : "+f"(c[0]), "+f"(c[1]), "+f"(c[2]), "+f"(c[3])
        : "r"(a[0]), "r"(a[1]), "r"(a[2]), "r"(a[3]), "r"(b[0]), "r"(b[1]));
}
__device__ __forceinline__ void ldsm4(uint32_t* r, uint32_t addr) {
    asm volatile("ldmatrix.sync.aligned.m8n8.x4.shared.b16 {%0,%1,%2,%3}, [%4];"
        : "=r"(r[0]), "=r"(r[1]), "=r"(r[2]), "=r"(r[3]) : "r"(addr));
}
__device__ __forceinline__ void ldsm4t(uint32_t* r, uint32_t addr) {
    asm volatile("ldmatrix.sync.aligned.m8n8.x4.trans.shared.b16 {%0,%1,%2,%3}, [%4];"
        : "=r"(r[0]), "=r"(r[1]), "=r"(r[2]), "=r"(r[3]) : "r"(addr));
}
#define CP_ASYNC16(dst, src) \
    asm volatile("cp.async.cg.shared.global [%0], [%1], 16;" :: "r"(dst), "l"(src))
#define CP_COMMIT() asm volatile("cp.async.commit_group;" ::: "memory")
#define CP_WAIT0()  asm volatile("cp.async.wait_group 0;" ::: "memory")

// ---------------- smem layout (bytes) ----------------
// SA: [128 t][264] fp16 (A full-K; later probs at pitch 272B), pitch 528B
// SB: [128 j][264] fp16 (U full), pitch 528B
// epilogue f32 [128][264] overlays SA+SB
#define SA 0u
#define SB 67584u
#define OFF_SSU 135168u
#define OFF_SSH 135680u
#define OFF_RM  136192u
#define OFF_RS  137216u
#define OFF_WHU 138240u
#define OFF_WH  139264u
#define OFF_SBM 140288u   // [128] rowmax (f32)
#define OFF_SLM 140800u   // scalar localM (padded 16B)
#define OFF_SQ  140816u   // [8][256] f32 partial-q2c reduce
#define SMEM_TOTAL 149008u

// ---------------- U fp16 convert + su (512 blocks, 16 rows each) ----------------
__global__ void usplit_kernel(const float* __restrict__ U, const float* __restrict__ w_u) {
    __shared__ float sSu[16];
    int b = blockIdx.x >> 3, jc = blockIdx.x & 7;
    int tid = threadIdx.x, lane = tid & 31;
    float wu = w_u[tid];
    if (tid < 16) sSu[tid] = 0.f;
    __syncthreads();
    const float* Ub = U + (size_t)b * JJ * DD;
    __half* uh = g_Uh + (size_t)b * JJ * DD;
    #pragma unroll
    for (int r = 0; r < 16; r++) {
        int j = jc * 16 + r;
        float v = Ub[j * DD + tid];
        uh[j * DD + tid] = __float2half_rn(v);
        float p = v * wu;
        #pragma unroll
        for (int o = 16; o; o >>= 1) p += __shfl_xor_sync(0xffffffffu, p, o);
        if (lane == 0) atomicAdd(&sSu[r], p);
    }
    __syncthreads();
    if (tid < 16) g_su[b * JJ + jc * 16 + tid] = sSu[tid];
}

// ---------------- main fused kernel ----------------
__global__ void __launch_bounds__(256, 1)
bidaf_main(const float* __restrict__ H, const float* __restrict__ w_h,
           const float* __restrict__ w_hu, float* __restrict__ G) {
    extern __shared__ char smem[];
    const uint32_t sbase = (uint32_t)__cvta_generic_to_shared(smem);
    const int b = blockIdx.y;
    const int t0 = blockIdx.x * TM;
    const int tid = threadIdx.x;
    const int wid = tid >> 5, lane = tid & 31;
    const int g = lane >> 2, qt = lane & 3;
    const int l16 = lane & 15, lh = lane >> 4;

    float* ssu  = (float*)(smem + OFF_SSU);
    float* ssh  = (float*)(smem + OFF_SSH);
    float* sRM  = (float*)(smem + OFF_RM);
    float* sRS  = (float*)(smem + OFF_RS);
    float* sWhu = (float*)(smem + OFF_WHU);
    float* sWh  = (float*)(smem + OFF_WH);
    float* sBM  = (float*)(smem + OFF_SBM);
    float* sLM  = (float*)(smem + OFF_SLM);
    float* sQ   = (float*)(smem + OFF_SQ);

    // ---- cp.async U [128 j][256 d] fp16 into SB (pitch 528B) ----
    {
        const char* src = (const char*)(g_Uh + (size_t)b * JJ * DD);
        #pragma unroll
        for (int k = 0; k < 16; k++) {
            int idx = tid + 256 * k;
            int j = idx >> 5, c = idx & 31;
            CP_ASYNC16(sbase + SB + (uint32_t)(j * 528 + c * 16), src + j * 512 + c * 16);
        }
        CP_COMMIT();
    }

    sWhu[tid] = w_hu[tid];
    sWh[tid]  = w_h[tid];
    if (tid < JJ) ssu[tid] = g_su[b * JJ + tid];
    __syncthreads();

    // ---- stage A = fp16(H*w_hu) full-K [128][256] + sh accum + G quarter0 store ----
    float shreg[16];
    {
        const float4* H4 = (const float4*)(H + ((size_t)(b * TT + t0)) * DD);
        #pragma unroll
        for (int rk = 0; rk < 16; rk++) {
            int row = wid + 8 * rk;
            size_t rowg = (size_t)(b * TT + t0 + row);
            float* G0 = G + rowg * (4 * DD);
            float sh = 0.f;
            #pragma unroll
            for (int h = 0; h < 2; h++) {
                int d = h * 128 + lane * 4;
                float4 v = H4[row * 64 + (d >> 2)];
                __half2 p01 = __floats2half2_rn(v.x * sWhu[d],     v.y * sWhu[d + 1]);
                __half2 p23 = __floats2half2_rn(v.z * sWhu[d + 2], v.w * sWhu[d + 3]);
                *(uint2*)(smem + SA + row * 528 + d * 2) =
                    make_uint2(*(uint32_t*)&p01, *(uint32_t*)&p23);
                *(float4*)&G0[d] = v;   // G quarter 0 = H (overlaps with GEMM1)
                sh += v.x * sWh[d] + v.y * sWh[d + 1] + v.z * sWh[d + 2] + v.w * sWh[d + 3];
            }
            #pragma unroll
            for (int o = 16; o; o >>= 1) sh += __shfl_xor_sync(0xffffffffu, sh, o);
            shreg[rk] = sh;
        }
    }
    if (lane == 0) {
        #pragma unroll
        for (int k = 0; k < 16; k++) ssh[wid + 8 * k] = shreg[k];
    }

    const int wm1 = wid >> 1, wn1 = wid & 1;   // 4x2 warp grid, 32x64 tiles
    float C1[2][8][4];
    #pragma unroll
    for (int mf = 0; mf < 2; mf++)
        #pragma unroll
        for (int nf = 0; nf < 8; nf++)
            #pragma unroll
            for (int q = 0; q < 4; q++) C1[mf][nf][q] = 0.f;

    CP_WAIT0();
    __syncthreads();

    // ================= GEMM1: S[128t][128j], K=256, single pass =================
    #pragma unroll
    for (int ks = 0; ks < 16; ks++) {
        uint32_t a[2][4];
        #pragma unroll
        for (int mf = 0; mf < 2; mf++) {
            uint32_t ar = sbase + SA + (uint32_t)((wm1 * 32 + mf * 16 + l16) * 528 + ks * 32 + lh * 16);
            ldsm4(a[mf], ar);
        }
        #pragma unroll
        for (int p = 0; p < 4; p++) {
            uint32_t br = sbase + SB + (uint32_t)((wn1 * 64 + p * 16 + l16) * 528 + ks * 32 + lh * 16);
            uint32_t bb[4];
            ldsm4(bb, br);
            uint32_t B0[2] = {bb[0], bb[2]}, B1[2] = {bb[1], bb[3]};
            #pragma unroll
            for (int mf = 0; mf < 2; mf++) {
                mma16816(C1[mf][2*p],   a[mf], B0);
                mma16816(C1[mf][2*p+1], a[mf], B1);
            }
        }
    }
    __syncthreads();   // A dead; SA reused for probs below

    // ================= softmax over j =================
    #pragma unroll
    for (int mf = 0; mf < 2; mf++) {
        int r0 = wm1 * 32 + mf * 16 + g;
        float m0 = -1e30f, m1 = -1e30f;
        #pragma unroll
        for (int nf = 0; nf < 8; nf++) {
            float2 su2 = *(const float2*)&ssu[wn1 * 64 + nf * 8 + qt * 2];
            C1[mf][nf][0] += su2.x; C1[mf][nf][1] += su2.y;
            C1[mf][nf][2] += su2.x; C1[mf][nf][3] += su2.y;
            m0 = fmaxf(m0, fmaxf(C1[mf][nf][0], C1[mf][nf][1]));
            m1 = fmaxf(m1, fmaxf(C1[mf][nf][2], C1[mf][nf][3]));
        }
        #pragma unroll
        for (int o = 1; o < 4; o <<= 1) {
            m0 = fmaxf(m0, __shfl_xor_sync(0xffffffffu, m0, o));
            m1 = fmaxf(m1, __shfl_xor_sync(0xffffffffu, m1, o));
        }
        if (qt == 0) { sRM[r0 * 2 + wn1] = m0; sRM[(r0 + 8) * 2 + wn1] = m1; }
    }
    __syncthreads();
    #pragma unroll
    for (int mf = 0; mf < 2; mf++) {
        int r0 = wm1 * 32 + mf * 16 + g;
        float M0 = fmaxf(sRM[r0 * 2], sRM[r0 * 2 + 1]);
        float M1 = fmaxf(sRM[(r0 + 8) * 2], sRM[(r0 + 8) * 2 + 1]);
        float s0 = 0.f, s1 = 0.f;
        #pragma unroll
        for (int nf = 0; nf < 8; nf++) {
            C1[mf][nf][0] = __expf(C1[mf][nf][0] - M0);
            C1[mf][nf][1] = __expf(C1[mf][nf][1] - M0);
            C1[mf][nf][2] = __expf(C1[mf][nf][2] - M1);
            C1[mf][nf][3] = __expf(C1[mf][nf][3] - M1);
            s0 += C1[mf][nf][0] + C1[mf][nf][1];
            s1 += C1[mf][nf][2] + C1[mf][nf][3];
        }
        #pragma unroll
        for (int o = 1; o < 4; o <<= 1) {
            s0 += __shfl_xor_sync(0xffffffffu, s0, o);
            s1 += __shfl_xor_sync(0xffffffffu, s1, o);
        }
        if (qt == 0) {
            sRS[r0 * 2 + wn1] = s0; sRS[(r0 + 8) * 2 + wn1] = s1;
            if (wn1 == 0) {
                float rm0 = M0 + ssh[r0], rm1 = M1 + ssh[r0 + 8];
                g_rowmax[b * TT + t0 + r0]     = rm0;
                g_rowmax[b * TT + t0 + r0 + 8] = rm1;
                sBM[r0] = rm0; sBM[r0 + 8] = rm1;
            }
        }
    }
    __syncthreads();
    // normalize + pack probs fp16 into SA (pitch 272B)
    #pragma unroll
    for (int mf = 0; mf < 2; mf++) {
        int r0 = wm1 * 32 + mf * 16 + g;
        float inv0 = 1.f / (sRS[r0 * 2] + sRS[r0 * 2 + 1]);
        float inv1 = 1.f / (sRS[(r0 + 8) * 2] + sRS[(r0 + 8) * 2 + 1]);
        #pragma unroll
        for (int nf = 0; nf < 8; nf++) {
            int col = wn1 * 64 + nf * 8 + qt * 2;
            __half2 p0 = __floats2half2_rn(C1[mf][nf][0] * inv0, C1[mf][nf][1] * inv0);
            __half2 p1 = __floats2half2_rn(C1[mf][nf][2] * inv1, C1[mf][nf][3] * inv1);
            *(uint32_t*)(smem + SA + r0 * 272 + col * 2)       = *(uint32_t*)&p0;
            *(uint32_t*)(smem + SA + (r0 + 8) * 272 + col * 2) = *(uint32_t*)&p1;
        }
    }
    // warp 0: local max over the 128 rowmax values (for split-softmax partials)
    if (tid < 32) {
        float m = fmaxf(fmaxf(sBM[tid], sBM[tid + 32]), fmaxf(sBM[tid + 64], sBM[tid + 96]));
        #pragma unroll
        for (int o = 16; o; o >>= 1) m = fmaxf(m, __shfl_xor_sync(0xffffffffu, m, o));
        if (tid == 0) sLM[0] = m;
    }
    __syncthreads();

    // ================= GEMM2: C2Q[128t][256d] = P @ U (trans-B on U) =================
    const int wm2 = wid >> 2, wn2 = wid & 3;   // 2x4 warp grid, 64x64 tiles
    float C2[4][8][4];
    #pragma unroll
    for (int mf = 0; mf < 4; mf++)
        #pragma unroll
        for (int nf = 0; nf < 8; nf++)
            #pragma unroll
            for (int q = 0; q < 4; q++) C2[mf][nf][q] = 0.f;

    #pragma unroll
    for (int ks = 0; ks < 8; ks++) {
        uint32_t a[4][4];
        #pragma unroll
        for (int mf = 0; mf < 4; mf++) {
            uint32_t ar = sbase + SA + (uint32_t)((wm2 * 64 + mf * 16 + l16) * 272 + ks * 32 + lh * 16);
            ldsm4(a[mf], ar);
        }
        #pragma unroll
        for (int p = 0; p < 4; p++) {
            uint32_t br = sbase + SB + (uint32_t)((ks * 16 + l16) * 528
                                                  + (wn2 * 64 + p * 16 + lh * 8) * 2);
            uint32_t bb[4];
            ldsm4t(bb, br);
            uint32_t B0[2] = {bb[0], bb[1]}, B1[2] = {bb[2], bb[3]};
            #pragma unroll
            for (int mf = 0; mf < 4; mf++) {
                mma16816(C2[mf][2*p],   a[mf], B0);
                mma16816(C2[mf][2*p+1], a[mf], B1);
            }
        }
    }
    __syncthreads();   // SA+SB dead -> f32 epilogue buffer overlays from 0

    // ================= epilogue: G quarters 1,2 + partial Q2C =================
    {
        float* sEpi = (float*)smem;            // [128][264] f32
        #pragma unroll
        for (int mf = 0; mf < 4; mf++) {
            int r0 = wm2 * 64 + mf * 16 + g;
            #pragma unroll
            for (int nf = 0; nf < 8; nf++) {
                int c0 = wn2 * 64 + nf * 8 + qt * 2;
                *(float2*)&sEpi[r0 * 264 + c0]       = make_float2(C2[mf][nf][0], C2[mf][nf][1]);
                *(float2*)&sEpi[(r0 + 8) * 264 + c0] = make_float2(C2[mf][nf][2], C2[mf][nf][3]);
            }
        }
        __syncthreads();
        const float localM = sLM[0];
        float4 qa0 = make_float4(0.f, 0.f, 0.f, 0.f);
        float4 qa1 = make_float4(0.f, 0.f, 0.f, 0.f);
        #pragma unroll 2
        for (int r = 0; r < 16; r++) {
            int row = wid * 16 + r;
            float wgt = __expf(sBM[row] - localM);
            size_t rowg = (size_t)(b * TT + t0 + row);
            const float* Hrow = H + rowg * DD;
            float* Grow = G + rowg * (4 * DD);
            #pragma unroll
            for (int i = 0; i < 2; i++) {
                int d = lane * 4 + 128 * i;
                float4 cq = *(float4*)&sEpi[row * 264 + d];
                float4 h = *(const float4*)&Hrow[d];
                *(float4*)&Grow[DD + d] = cq;
                *(float4*)&Grow[2 * DD + d] = make_float4(h.x*cq.x, h.y*cq.y, h.z*cq.z, h.w*cq.w);
                if (i == 0) { qa0.x += wgt*h.x; qa0.y += wgt*h.y; qa0.z += wgt*h.z; qa0.w += wgt*h.w; }
                else        { qa1.x += wgt*h.x; qa1.y += wgt*h.y; qa1.z += wgt*h.z; qa1.w += wgt*h.w; }
            }
        }
        *(float4*)&sQ[wid * 256 + lane * 4]       = qa0;
        *(float4*)&sQ[wid * 256 + lane * 4 + 128] = qa1;
        __syncthreads();
        {
            float s = 0.f;
            #pragma unroll
            for (int w = 0; w < 8; w++) s += sQ[w * 256 + tid];
            g_q2cp[(size_t)(b * 8 + blockIdx.x) * DD + tid] = s;
        }
    }
}

// ---------------- G quarter 3 = H * Q2C, with fused per-block Q2C recombine ----------------
// grid 4096 (16 bt-rows per block, all same b = blockIdx.x >> 6)
__global__ void g3_kernel(const float* __restrict__ H, float* __restrict__ G) {
    __shared__ float sM[8], sS[8], sQ[DD];
    int tid = threadIdx.x;
    int w = tid >> 5, lane = tid & 31;
    int b = blockIdx.x >> 6;

    // warp w: chunk-w max and sumexp from g_rowmax
    {
        float v[4], m = -1e30f;
        #pragma unroll
        for (int k = 0; k < 4; k++) {
            v[k] = g_rowmax[b * TT + w * 128 + lane + 32 * k];
            m = fmaxf(m, v[k]);
        }
        #pragma unroll
        for (int o = 16; o; o >>= 1) m = fmaxf(m, __shfl_xor_sync(0xffffffffu, m, o));
        float s = 0.f;
        #pragma unroll
        for (int k = 0; k < 4; k++) s += __expf(v[k] - m);
        #pragma unroll
        for (int o = 16; o; o >>= 1) s += __shfl_xor_sync(0xffffffffu, s, o);
        if (lane == 0) { sM[w] = m; sS[w] = s; }
    }
    __syncthreads();
    {
        float Mg = sM[0];
        #pragma unroll
        for (int c = 1; c < 8; c++) Mg = fmaxf(Mg, sM[c]);
        float denom = 0.f, acc = 0.f;
        #pragma unroll
        for (int c = 0; c < 8; c++) {
            float sc = __expf(sM[c] - Mg);
            denom += sc * sS[c];
            acc   += sc * g_q2cp[(size_t)(b * 8 + c) * DD + tid];
        }
        sQ[tid] = acc / denom;
    }
    __syncthreads();

    size_t base = (size_t)blockIdx.x * 1024 + tid;
    #pragma unroll
    for (int k = 0; k < 4; k++) {
        size_t idx = base + 256 * k;           // float4 units
        int d4 = (int)(idx & 63);
        size_t bt = idx >> 6;
        float4 h = ((const float4*)H)[idx];
        float4 q = *(float4*)&sQ[d4 * 4];
        float4 o = make_float4(h.x * q.x, h.y * q.y, h.z * q.z, h.w * q.w);
        ((float4*)G)[bt * 256 + 192 + d4] = o;
    }
}

extern "C" void kernel_launch(void* const* d_in, const int* in_sizes, int n_in,
                              void* d_out, int out_size) {
    const float* H    = (const float*)d_in[0];
    const float* U    = (const float*)d_in[1];
    const float* w_h  = (const float*)d_in[2];
    const float* w_u  = (const float*)d_in[3];
    const float* w_hu = (const float*)d_in[4];
    float* G = (float*)d_out;

    cudaFuncSetAttribute(bidaf_main, cudaFuncAttributeMaxDynamicSharedMemorySize, SMEM_TOTAL);

    usplit_kernel<<<BB * 8, 256>>>(U, w_u);
    bidaf_main<<<dim3(TT / TM, BB), 256, SMEM_TOTAL>>>(H, w_h, w_hu, G);
    g3_kernel<<<4096, 256>>>(H, G);
}